// round 6
// baseline (speedup 1.0000x reference)
#include <cuda_runtime.h>
#include <cuda_bf16.h>
#include <cstdint>

// Problem constants
#define BB 2
#define TT 2048
#define CC 1024
#define HH 16
#define HD 64
#define ROWS (BB*TT)          // 4096
#define C3 (3*CC)             // 3072

// Scratch (allocation-free: __device__ globals)
__device__ float g_qkv[(size_t)ROWS * C3];   // tf32-rounded q|k|v (natural layout)
__device__ float g_att[(size_t)ROWS * CC];   // tf32-rounded, k-permuted attention out
__device__ float g_xp[(size_t)ROWS * CC];    // tf32-rounded, k-permuted x
__device__ float g_wqt[(size_t)C3 * CC];     // Wqkv^T [3072][1024], tf32, k-permuted
__device__ float g_wot[(size_t)CC * CC];     // Wo^T   [1024][1024], tf32, k-permuted

// ---------------------------------------------------------------------------
// helpers
// ---------------------------------------------------------------------------
__device__ __forceinline__ float to_tf32(float x) {
    float y;
    asm("cvt.rna.tf32.f32 %0, %1;" : "=f"(y) : "f"(x));
    return y;
}

__device__ __forceinline__ void mma_tf32(float& d0, float& d1, float& d2, float& d3,
                                         float a0, float a1, float a2, float a3,
                                         float b0, float b1) {
    asm volatile(
        "mma.sync.aligned.m16n8k8.row.col.f32.tf32.tf32.f32 "
        "{%0,%1,%2,%3}, {%4,%5,%6,%7}, {%8,%9}, {%0,%1,%2,%3};"
        : "+f"(d0), "+f"(d1), "+f"(d2), "+f"(d3)
        : "r"(__float_as_uint(a0)), "r"(__float_as_uint(a1)),
          "r"(__float_as_uint(a2)), "r"(__float_as_uint(a3)),
          "r"(__float_as_uint(b0)), "r"(__float_as_uint(b1)));
}

__device__ __forceinline__ void cp16(void* dst, const float* src) {
    uint32_t d = (uint32_t)__cvta_generic_to_shared(dst);
    asm volatile("cp.async.cg.shared.global [%0], [%1], 16;" :: "r"(d), "l"(src));
}
#define CP_COMMIT() asm volatile("cp.async.commit_group;")

// ---------------------------------------------------------------------------
// prep: k-permute (within-8 interleave) + tf32 round.
// Position layout per 8-group: [k0,k4,k1,k5,k2,k6,k3,k7], i.e. original k at
// t (<4) lands at 2t, k at t+4 lands at 2t+1 -> mma frag pairs are adjacent.
// ---------------------------------------------------------------------------
__global__ void perm_round8(const float4* __restrict__ in, float4* __restrict__ out, int n8) {
    int i = blockIdx.x * 256 + threadIdx.x;
    if (i < n8) {
        float4 a = in[2 * i], b = in[2 * i + 1];
        float4 o0 = make_float4(to_tf32(a.x), to_tf32(b.x), to_tf32(a.y), to_tf32(b.y));
        float4 o1 = make_float4(to_tf32(a.z), to_tf32(b.z), to_tf32(a.w), to_tf32(b.w));
        out[2 * i]     = o0;
        out[2 * i + 1] = o1;
    }
}

// W [K][N] row-major -> T [N][K] with permuted k, tf32-rounded
__global__ void transpose_perm(const float* __restrict__ W, float* __restrict__ T,
                               int K, int N) {
    __shared__ float tile[32][33];
    int x = blockIdx.x * 32 + threadIdx.x;   // n
    int y0 = blockIdx.y * 32;                // k base
    #pragma unroll
    for (int j = threadIdx.y; j < 32; j += 8)
        tile[j][threadIdx.x] = W[(size_t)(y0 + j) * N + x];
    __syncthreads();
    int k = y0 + threadIdx.x;
    int k7 = k & 7;
    int kp = (k & ~7) | ((k7 < 4) ? 2 * k7 : 2 * k7 - 7);
    #pragma unroll
    for (int j = threadIdx.y; j < 32; j += 8) {
        int n = blockIdx.x * 32 + j;
        T[(size_t)n * K + kp] = to_tf32(tile[threadIdx.x][j]);
    }
}

// ---------------------------------------------------------------------------
// tf32 tensor-core GEMM, both operands K-major & k-permuted in gmem.
// C[M,N] = A[M,K] @ B[N,K]^T. Block tile 128x128x32, 8 warps (2m x 4n),
// warp tile 64x32. Smem: As/Bs both [128 rows][GST=40] (40%32==8 ->
// LDS.64 frag loads conflict-free, bank-pair (4g+t)%16 bijective).
// 2-stage cp.async pipeline. roundOut rounds C to tf32.
// ---------------------------------------------------------------------------
#define GST 40
#define GT_SZ (128*GST)

__global__ __launch_bounds__(256, 2) void tgemm(const float* __restrict__ A,
                                                const float* __restrict__ B,
                                                float* __restrict__ C,
                                                int N_out, int K, int roundOut) {
    extern __shared__ float sm[];   // [2][A tile | B tile]

    const int tid  = threadIdx.x;
    const int warp = tid >> 5;
    const int lane = tid & 31;
    const int g = lane >> 2;
    const int t = lane & 3;
    const int wm = (warp >> 2) * 64;
    const int wn = (warp & 3) * 32;
    const int row0 = blockIdx.y * 128;
    const int col0 = blockIdx.x * 128;

    float acc[4][4][4];
    #pragma unroll
    for (int i = 0; i < 4; i++)
        #pragma unroll
        for (int j = 0; j < 4; j++)
            #pragma unroll
            for (int r = 0; r < 4; r++) acc[i][j][r] = 0.f;

    const int NK = K >> 5;

    auto stage = [&](int kt, int s) {
        float* Ad = sm + s * 2 * GT_SZ;
        float* Bd = Ad + GT_SZ;
        #pragma unroll
        for (int i = 0; i < 4; i++) {
            int id = tid + i * 256;
            int r = id >> 3, k4 = (id & 7) * 4;
            cp16(Ad + r * GST + k4, A + (size_t)(row0 + r) * K + kt + k4);
        }
        #pragma unroll
        for (int i = 0; i < 4; i++) {
            int id = tid + i * 256;
            int r = id >> 3, k4 = (id & 7) * 4;
            cp16(Bd + r * GST + k4, B + (size_t)(col0 + r) * K + kt + k4);
        }
        CP_COMMIT();
    };

    stage(0, 0);

    for (int it = 0; it < NK; it++) {
        const int s = it & 1;
        if (it + 1 < NK) {
            stage((it + 1) * 32, s ^ 1);
            asm volatile("cp.async.wait_group 1;");
        } else {
            asm volatile("cp.async.wait_group 0;");
        }
        __syncthreads();

        const float* Ac = sm + s * 2 * GT_SZ;
        const float* Bc = Ac + GT_SZ;

        #pragma unroll
        for (int ks = 0; ks < 4; ks++) {
            const int k0 = ks * 8;
            float2 af0[4], af1[4], bf[4];
            #pragma unroll
            for (int mt = 0; mt < 4; mt++) {
                int r = wm + mt * 16 + g;
                af0[mt] = *(const float2*)(Ac + (r    ) * GST + k0 + 2 * t);
                af1[mt] = *(const float2*)(Ac + (r + 8) * GST + k0 + 2 * t);
            }
            #pragma unroll
            for (int nt = 0; nt < 4; nt++) {
                int c = wn + nt * 8 + g;
                bf[nt] = *(const float2*)(Bc + c * GST + k0 + 2 * t);
            }
            #pragma unroll
            for (int mt = 0; mt < 4; mt++)
                #pragma unroll
                for (int nt = 0; nt < 4; nt++)
                    mma_tf32(acc[mt][nt][0], acc[mt][nt][1], acc[mt][nt][2], acc[mt][nt][3],
                             af0[mt].x, af1[mt].x, af0[mt].y, af1[mt].y,
                             bf[nt].x, bf[nt].y);
        }
        __syncthreads();
    }

    #pragma unroll
    for (int mt = 0; mt < 4; mt++) {
        int r = row0 + wm + mt * 16 + g;
        #pragma unroll
        for (int nt = 0; nt < 4; nt++) {
            int c = col0 + wn + nt * 8 + 2 * t;
            float v0 = acc[mt][nt][0], v1 = acc[mt][nt][1];
            float v2 = acc[mt][nt][2], v3 = acc[mt][nt][3];
            if (roundOut) { v0 = to_tf32(v0); v1 = to_tf32(v1); v2 = to_tf32(v2); v3 = to_tf32(v3); }
            *(float2*)&C[(size_t)r * N_out + c]       = make_float2(v0, v1);
            *(float2*)&C[(size_t)(r + 8) * N_out + c] = make_float2(v2, v3);
        }
    }
}

// ---------------------------------------------------------------------------
// Tensor-core causal flash attention (R4 core, proven). Epilogue writes att
// k-permuted + tf32-rounded for the O-GEMM.
// ---------------------------------------------------------------------------
#define KST 68
#define VST 72
#define PST 72
#define KS_SZ (64*KST)
#define VS_SZ (64*VST)

__global__ __launch_bounds__(256, 2) void attn_tc(const float* __restrict__ qkv,
                                                  float* __restrict__ att) {
    extern __shared__ float sm[];
    float* Ks = sm;
    float* Vs = sm + 2 * KS_SZ;
    float* Ps = sm + 2 * KS_SZ + 2 * VS_SZ;

    const int b   = blockIdx.x >> 4;
    const int h   = blockIdx.x & 15;
    const int qb  = (gridDim.y - 1) - blockIdx.y;
    const int qt0 = qb * 128;
    const int tid  = threadIdx.x;
    const int warp = tid >> 5;
    const int lane = tid & 31;
    const int g = lane >> 2;
    const int t = lane & 3;
    const int wrow = warp * 16;
    const float scale = 0.03125f;

    float qa[8][4];
    {
        const float* qp0 = qkv + ((size_t)(b * TT + qt0 + wrow + g)) * C3 + h * HD;
        const float* qp1 = qp0 + 8 * (size_t)C3;
        #pragma unroll
        for (int kc = 0; kc < 8; kc++) {
            qa[kc][0] = qp0[kc * 8 + t]     * scale;
            qa[kc][1] = qp1[kc * 8 + t]     * scale;
            qa[kc][2] = qp0[kc * 8 + t + 4] * scale;
            qa[kc][3] = qp1[kc * 8 + t + 4] * scale;
        }
    }

    float o[8][4];
    #pragma unroll
    for (int i = 0; i < 8; i++)
        #pragma unroll
        for (int r = 0; r < 4; r++) o[i][r] = 0.f;
    float m0 = -1e30f, m1 = -1e30f, l0 = 0.f, l1 = 0.f;

    const int ntiles = 2 * qb + 2;

    auto prefetch = [&](int tile, int stage) {
        const int kt0 = tile * 64;
        const float* kb = qkv + ((size_t)(b * TT + kt0)) * C3 + CC + h * HD;
        const float* vb = kb + CC;
        float* Kd = Ks + stage * KS_SZ;
        float* Vd = Vs + stage * VS_SZ;
        #pragma unroll
        for (int i = 0; i < 4; i++) {
            int id = tid + i * 256;
            int r = id >> 4, c4 = (id & 15) * 4;
            cp16(Kd + r * KST + c4, kb + (size_t)r * C3 + c4);
            cp16(Vd + r * VST + c4, vb + (size_t)r * C3 + c4);
        }
        CP_COMMIT();
    };

    prefetch(0, 0);

    for (int tile = 0; tile < ntiles; tile++) {
        const int stage = tile & 1;
        const int kt0 = tile * 64;
        if (tile + 1 < ntiles) {
            prefetch(tile + 1, stage ^ 1);
            asm volatile("cp.async.wait_group 1;");
        } else {
            asm volatile("cp.async.wait_group 0;");
        }
        __syncthreads();

        const float* Kc = Ks + stage * KS_SZ;
        const float* Vc = Vs + stage * VS_SZ;

        float s[8][4];
        #pragma unroll
        for (int i = 0; i < 8; i++)
            #pragma unroll
            for (int r = 0; r < 4; r++) s[i][r] = 0.f;
        #pragma unroll
        for (int kc = 0; kc < 8; kc++) {
            #pragma unroll
            for (int nt = 0; nt < 8; nt++) {
                const float* kr = Kc + (nt * 8 + g) * KST + kc * 8 + t;
                mma_tf32(s[nt][0], s[nt][1], s[nt][2], s[nt][3],
                         qa[kc][0], qa[kc][1], qa[kc][2], qa[kc][3],
                         kr[0], kr[4]);
            }
        }

        if (tile >= 2 * qb) {
            const int q0 = qt0 + wrow + g;
            const int q1 = q0 + 8;
            #pragma unroll
            for (int nt = 0; nt < 8; nt++) {
                int kcol = kt0 + nt * 8 + 2 * t;
                if (kcol     > q0) s[nt][0] = -1e30f;
                if (kcol + 1 > q0) s[nt][1] = -1e30f;
                if (kcol     > q1) s[nt][2] = -1e30f;
                if (kcol + 1 > q1) s[nt][3] = -1e30f;
            }
        }

        float mt0 = -1e30f, mt1 = -1e30f;
        #pragma unroll
        for (int nt = 0; nt < 8; nt++) {
            mt0 = fmaxf(mt0, fmaxf(s[nt][0], s[nt][1]));
            mt1 = fmaxf(mt1, fmaxf(s[nt][2], s[nt][3]));
        }
        mt0 = fmaxf(mt0, __shfl_xor_sync(0xffffffffu, mt0, 1));
        mt0 = fmaxf(mt0, __shfl_xor_sync(0xffffffffu, mt0, 2));
        mt1 = fmaxf(mt1, __shfl_xor_sync(0xffffffffu, mt1, 1));
        mt1 = fmaxf(mt1, __shfl_xor_sync(0xffffffffu, mt1, 2));

        const float mn0 = fmaxf(m0, mt0);
        const float mn1 = fmaxf(m1, mt1);
        const float c0 = __expf(m0 - mn0);
        const float c1 = __expf(m1 - mn1);
        float sum0 = 0.f, sum1 = 0.f;
        #pragma unroll
        for (int nt = 0; nt < 8; nt++) {
            s[nt][0] = __expf(s[nt][0] - mn0); sum0 += s[nt][0];
            s[nt][1] = __expf(s[nt][1] - mn0); sum0 += s[nt][1];
            s[nt][2] = __expf(s[nt][2] - mn1); sum1 += s[nt][2];
            s[nt][3] = __expf(s[nt][3] - mn1); sum1 += s[nt][3];
        }
        sum0 += __shfl_xor_sync(0xffffffffu, sum0, 1);
        sum0 += __shfl_xor_sync(0xffffffffu, sum0, 2);
        sum1 += __shfl_xor_sync(0xffffffffu, sum1, 1);
        sum1 += __shfl_xor_sync(0xffffffffu, sum1, 2);
        l0 = l0 * c0 + sum0;
        l1 = l1 * c1 + sum1;
        m0 = mn0; m1 = mn1;

        #pragma unroll
        for (int dt = 0; dt < 8; dt++) {
            o[dt][0] *= c0; o[dt][1] *= c0;
            o[dt][2] *= c1; o[dt][3] *= c1;
        }

        float* pr0 = Ps + (wrow + g) * PST;
        float* pr1 = pr0 + 8 * PST;
        #pragma unroll
        for (int nt = 0; nt < 8; nt++) {
            *(float2*)(pr0 + nt * 8 + 2 * t) = make_float2(to_tf32(s[nt][0]), to_tf32(s[nt][1]));
            *(float2*)(pr1 + nt * 8 + 2 * t) = make_float2(to_tf32(s[nt][2]), to_tf32(s[nt][3]));
        }
        __syncwarp();

        #pragma unroll
        for (int kc = 0; kc < 8; kc++) {
            float a0 = pr0[kc * 8 + t];
            float a1 = pr1[kc * 8 + t];
            float a2 = pr0[kc * 8 + t + 4];
            float a3 = pr1[kc * 8 + t + 4];
            #pragma unroll
            for (int dt = 0; dt < 8; dt++) {
                const float* vr0 = Vc + (kc * 8 + t    ) * VST + dt * 8 + g;
                const float* vr1 = Vc + (kc * 8 + t + 4) * VST + dt * 8 + g;
                mma_tf32(o[dt][0], o[dt][1], o[dt][2], o[dt][3],
                         a0, a1, a2, a3, vr0[0], vr1[0]);
            }
        }
        __syncthreads();
    }

    // epilogue: k-permuted + tf32-rounded att for the O-GEMM.
    // value at col d lands at position (d&~7) | perm(d&7).
    const float inv0 = 1.f / l0;
    const float inv1 = 1.f / l1;
    const size_t ob0 = ((size_t)(b * TT + qt0 + wrow + g)) * CC + h * HD;
    const size_t ob1 = ob0 + 8 * (size_t)CC;
    const int pa = (t < 2) ? 4 * t     : 4 * t - 7;   // perm(2t)
    const int pb = (t < 2) ? 4 * t + 2 : 4 * t - 5;   // perm(2t+1)
    #pragma unroll
    for (int dt = 0; dt < 8; dt++) {
        att[ob0 + dt * 8 + pa] = to_tf32(o[dt][0] * inv0);
        att[ob0 + dt * 8 + pb] = to_tf32(o[dt][1] * inv0);
        att[ob1 + dt * 8 + pa] = to_tf32(o[dt][2] * inv1);
        att[ob1 + dt * 8 + pb] = to_tf32(o[dt][3] * inv1);
    }
}

// ---------------------------------------------------------------------------
extern "C" void kernel_launch(void* const* d_in, const int* in_sizes, int n_in,
                              void* d_out, int out_size) {
    const float* x    = (const float*)d_in[0];   // [2,2048,1024]
    const float* Wqkv = (const float*)d_in[1];   // [1024,3072]
    const float* Wo   = (const float*)d_in[2];   // [1024,1024]
    float* out = (float*)d_out;                  // [2,2048,1024]

    float *qkv, *att, *xp, *wqt, *wot;
    cudaGetSymbolAddress((void**)&qkv, g_qkv);
    cudaGetSymbolAddress((void**)&att, g_att);
    cudaGetSymbolAddress((void**)&xp,  g_xp);
    cudaGetSymbolAddress((void**)&wqt, g_wqt);
    cudaGetSymbolAddress((void**)&wot, g_wot);

    const int SMEM_G = 2 * 2 * GT_SZ * (int)sizeof(float);                 // 81920
    const int SMEM_A = (2 * KS_SZ + 2 * VS_SZ + 128 * PST) * (int)sizeof(float);
    static int inited = 0;
    if (!inited) {
        cudaFuncSetAttribute(tgemm,   cudaFuncAttributeMaxDynamicSharedMemorySize, SMEM_G);
        cudaFuncSetAttribute(attn_tc, cudaFuncAttributeMaxDynamicSharedMemorySize, SMEM_A);
        inited = 1;
    }

    // 0) prep: permute+round x; transpose+permute+round weights
    perm_round8<<<(ROWS * CC / 8 + 255) / 256, 256>>>((const float4*)x, (float4*)xp, ROWS * CC / 8);
    transpose_perm<<<dim3(C3 / 32, CC / 32), dim3(32, 8)>>>(Wqkv, wqt, CC, C3);
    transpose_perm<<<dim3(CC / 32, CC / 32), dim3(32, 8)>>>(Wo, wot, CC, CC);

    // 1) qkv = x @ Wqkv  (epilogue rounds to tf32 for attention)
    tgemm<<<dim3(C3 / 128, ROWS / 128), 256, SMEM_G>>>(xp, wqt, qkv, C3, CC, 1);

    // 2) tensor-core causal flash attention (emits k-permuted att)
    attn_tc<<<dim3(BB * HH, TT / 128), 256, SMEM_A>>>(qkv, att);

    // 3) out = att @ Wo
    tgemm<<<dim3(CC / 128, ROWS / 128), 256, SMEM_G>>>(att, wot, out, CC, CC, 0);
}

// round 7
// speedup vs baseline: 1.8473x; 1.8473x over previous
#include <cuda_runtime.h>
#include <cuda_fp16.h>
#include <cstdint>

// Problem constants
#define BB 2
#define TT 2048
#define CC 1024
#define HH 16
#define HD 64
#define ROWS 4096
#define C3 3072

// Scratch (allocation-free: __device__ globals)
__device__ __half g_q  [(size_t)ROWS * CC];       // Q fp16, natural layout
__device__ __half g_k  [(size_t)ROWS * CC];       // K fp16, x(1/32), d pair-permuted
__device__ __half g_vt [(size_t)BB * HH * HD * TT]; // V^T per (b,h): [bh][d][t'], token pair-permuted
__device__ __half g_att[(size_t)ROWS * CC];       // attention out fp16, d pair-permuted
__device__ __half g_xp [(size_t)ROWS * CC];       // x fp16, k pair-permuted
__device__ __half g_wqt[(size_t)C3 * CC];         // Wqkv^T fp16, k pair-permuted
__device__ __half g_wot[(size_t)CC * CC];         // Wo^T fp16, k pair-permuted

// ---------------------------------------------------------------------------
// helpers
// ---------------------------------------------------------------------------
__device__ __forceinline__ void mma_f16(float* d,
                                        uint32_t a0, uint32_t a1, uint32_t a2, uint32_t a3,
                                        uint32_t b0, uint32_t b1) {
    asm volatile(
        "mma.sync.aligned.m16n8k16.row.col.f32.f16.f16.f32 "
        "{%0,%1,%2,%3}, {%4,%5,%6,%7}, {%8,%9}, {%0,%1,%2,%3};"
        : "+f"(d[0]), "+f"(d[1]), "+f"(d[2]), "+f"(d[3])
        : "r"(a0), "r"(a1), "r"(a2), "r"(a3), "r"(b0), "r"(b1));
}

__device__ __forceinline__ void cp16(void* dst, const void* src) {
    uint32_t d = (uint32_t)__cvta_generic_to_shared(dst);
    asm volatile("cp.async.cg.shared.global [%0], [%1], 16;" :: "r"(d), "l"(src));
}
#define CP_COMMIT() asm volatile("cp.async.commit_group;")

// pair-permutation within 16-half groups: pair q -> slot [0,4,1,5,2,6,3,7]
__device__ __forceinline__ int pslot(int p) { return (p < 4) ? 2 * p : 2 * p - 7; }

// ---------------------------------------------------------------------------
// prep: fp16 + pair-permute over the contraction dim
// ---------------------------------------------------------------------------
__global__ void perm_half(const float4* __restrict__ in, __half* __restrict__ out, int n16) {
    int i = blockIdx.x * 256 + threadIdx.x;
    if (i < n16) {
        float a[16];
        #pragma unroll
        for (int j = 0; j < 4; j++) {
            float4 v = in[i * 4 + j];
            a[4 * j + 0] = v.x; a[4 * j + 1] = v.y;
            a[4 * j + 2] = v.z; a[4 * j + 3] = v.w;
        }
        uint32_t u[8];
        #pragma unroll
        for (int s = 0; s < 8; s++) {
            int q = (s & 1) ? (s + 7) >> 1 : s >> 1;   // inverse of pslot
            __half2 h = __floats2half2_rn(a[2 * q], a[2 * q + 1]);
            u[s] = *(uint32_t*)&h;
        }
        uint4* o = (uint4*)(out + (size_t)i * 16);
        o[0] = make_uint4(u[0], u[1], u[2], u[3]);
        o[1] = make_uint4(u[4], u[5], u[6], u[7]);
    }
}

// W [K][N] row-major -> T [N][K] fp16, k pair-permuted
__global__ void transpose_perm_half(const float* __restrict__ W, __half* __restrict__ T,
                                    int K, int N) {
    __shared__ float tile[32][33];
    int x = blockIdx.x * 32 + threadIdx.x;   // n
    int y0 = blockIdx.y * 32;                // k base
    #pragma unroll
    for (int j = threadIdx.y; j < 32; j += 8)
        tile[j][threadIdx.x] = W[(size_t)(y0 + j) * N + x];
    __syncthreads();
    int k = y0 + threadIdx.x;
    int kp = (k & ~15) | (pslot((k & 15) >> 1) << 1) | (k & 1);
    #pragma unroll
    for (int j = threadIdx.y; j < 32; j += 8) {
        int n = blockIdx.x * 32 + j;
        T[(size_t)n * K + kp] = __float2half_rn(tile[threadIdx.x][j]);
    }
}

// ---------------------------------------------------------------------------
// fp16 tensor-core GEMM, both operands K-major (K=1024), pair-permuted.
// C[M,N] = A[M,K] @ B[N,K]^T. Block 128x128, K-chunk 64 halves (128B rows),
// smem stride 160B -> all fragment LDS.64 conflict-free. 2-stage cp.async.
// mode 0: C fp32 natural. mode 1: QKV epilogue (writes g_q/g_k/g_vt).
// ---------------------------------------------------------------------------
#define TSTR   160
#define TILE_B (128 * TSTR)          // 20480
#define STG_B  (2 * TILE_B)
#define GSMEM  (2 * STG_B)           // 81920

__device__ __forceinline__ void write_qkv(int r, int c, float v0, float v1) {
    if (c < CC) {
        *(__half2*)&g_q[(size_t)r * CC + c] = __floats2half2_rn(v0, v1);
    } else if (c < 2 * CC) {
        int ck = c - CC;
        int pos = (ck & ~15) | (pslot((ck & 15) >> 1) << 1);
        *(__half2*)&g_k[(size_t)r * CC + pos] = __floats2half2_rn(v0 * 0.03125f, v1 * 0.03125f);
    } else {
        int vd = c - 2 * CC;
        int bh = (r >> 11) * HH + (vd >> 6);
        int d0 = vd & 63;
        int tt = r & 2047;
        int ptt = (tt & ~15) | (pslot((tt & 15) >> 1) << 1) | (tt & 1);
        g_vt[((size_t)bh * HD + d0    ) * TT + ptt] = __float2half_rn(v0);
        g_vt[((size_t)bh * HD + d0 + 1) * TT + ptt] = __float2half_rn(v1);
    }
}

__global__ __launch_bounds__(256, 2) void tgemm_f16(const __half* __restrict__ A,
                                                    const __half* __restrict__ B,
                                                    float* __restrict__ C,
                                                    int N_out, int mode) {
    extern __shared__ char sm[];

    const int tid  = threadIdx.x;
    const int warp = tid >> 5;
    const int lane = tid & 31;
    const int g = lane >> 2;
    const int t = lane & 3;
    const int wm = (warp >> 2) * 64;
    const int wn = (warp & 3) * 32;
    const int row0 = blockIdx.y * 128;
    const int col0 = blockIdx.x * 128;

    float acc[4][4][4];
    #pragma unroll
    for (int i = 0; i < 4; i++)
        #pragma unroll
        for (int j = 0; j < 4; j++)
            #pragma unroll
            for (int r = 0; r < 4; r++) acc[i][j][r] = 0.f;

    const char* Ab = (const char*)A;
    const char* Bb = (const char*)B;

    auto stage = [&](int chunk, int s) {
        char* As = sm + s * STG_B;
        char* Bs = As + TILE_B;
        const size_t koff = (size_t)chunk * 128;   // 64 halves = 128 B
        #pragma unroll
        for (int i = 0; i < 4; i++) {
            int id = tid + i * 256;
            int r = id >> 3, j = id & 7;
            cp16(As + r * TSTR + j * 16, Ab + (size_t)(row0 + r) * 2048 + koff + j * 16);
        }
        #pragma unroll
        for (int i = 0; i < 4; i++) {
            int id = tid + i * 256;
            int r = id >> 3, j = id & 7;
            cp16(Bs + r * TSTR + j * 16, Bb + (size_t)(col0 + r) * 2048 + koff + j * 16);
        }
        CP_COMMIT();
    };

    stage(0, 0);

    for (int it = 0; it < 16; it++) {
        const int s = it & 1;
        if (it + 1 < 16) {
            stage(it + 1, s ^ 1);
            asm volatile("cp.async.wait_group 1;");
        } else {
            asm volatile("cp.async.wait_group 0;");
        }
        __syncthreads();

        const char* As = sm + s * STG_B;
        const char* Bs = As + TILE_B;

        #pragma unroll
        for (int kc = 0; kc < 4; kc++) {
            uint2 a0[4], a1[4], bf[4];
            #pragma unroll
            for (int mt = 0; mt < 4; mt++) {
                const char* p = As + (wm + mt * 16 + g) * TSTR + kc * 32 + t * 8;
                a0[mt] = *(const uint2*)p;                 // (a0, a2) row r
                a1[mt] = *(const uint2*)(p + 8 * TSTR);    // (a1, a3) row r+8
            }
            #pragma unroll
            for (int nt = 0; nt < 4; nt++)
                bf[nt] = *(const uint2*)(Bs + (wn + nt * 8 + g) * TSTR + kc * 32 + t * 8);
            #pragma unroll
            for (int mt = 0; mt < 4; mt++)
                #pragma unroll
                for (int nt = 0; nt < 4; nt++)
                    mma_f16(acc[mt][nt], a0[mt].x, a1[mt].x, a0[mt].y, a1[mt].y,
                            bf[nt].x, bf[nt].y);
        }
        __syncthreads();
    }

    #pragma unroll
    for (int mt = 0; mt < 4; mt++) {
        int r = row0 + wm + mt * 16 + g;
        #pragma unroll
        for (int nt = 0; nt < 4; nt++) {
            int c = col0 + wn + nt * 8 + 2 * t;
            if (mode == 0) {
                *(float2*)&C[(size_t)r * N_out + c]       = make_float2(acc[mt][nt][0], acc[mt][nt][1]);
                *(float2*)&C[(size_t)(r + 8) * N_out + c] = make_float2(acc[mt][nt][2], acc[mt][nt][3]);
            } else {
                write_qkv(r,     c, acc[mt][nt][0], acc[mt][nt][1]);
                write_qkv(r + 8, c, acc[mt][nt][2], acc[mt][nt][3]);
            }
        }
    }
}

// ---------------------------------------------------------------------------
// fp16 tensor-core causal flash attention.
// Block: 128 query rows of one (b,h); 8 warps x 16 rows; key tiles of 64.
// Smem (byte offsets): K [2][64][160B], Vt [2][64][160B], P [128][160B].
// All fragment LDS.64 conflict-free (stride 160B -> banks 8g+2t).
// ---------------------------------------------------------------------------
#define K_ST   10240
#define ASMEM  (2 * K_ST + 2 * K_ST + 128 * TSTR)   // 61440

__global__ __launch_bounds__(256, 2) void attn_f16() {
    extern __shared__ char sm[];
    char* Ks = sm;                    // [2][10240]
    char* Vt = sm + 2 * K_ST;         // [2][10240]
    char* Ps = sm + 4 * K_ST;         // [128*160]

    const int b   = blockIdx.x >> 4;
    const int h   = blockIdx.x & 15;
    const int qb  = (gridDim.y - 1) - blockIdx.y;    // heavy blocks first
    const int qt0 = qb * 128;
    const int tid  = threadIdx.x;
    const int warp = tid >> 5;
    const int lane = tid & 31;
    const int g = lane >> 2;
    const int t = lane & 3;
    const int wrow = warp * 16;

    // Q fragments (fp16, natural layout; scale folded into K)
    uint32_t qa[4][4];
    {
        const size_t qb0 = ((size_t)(b * TT + qt0 + wrow + g)) * CC + h * HD;
        const size_t qb1 = qb0 + 8 * (size_t)CC;
        #pragma unroll
        for (int kc = 0; kc < 4; kc++) {
            qa[kc][0] = *(const uint32_t*)&g_q[qb0 + kc * 16 + 2 * t];
            qa[kc][1] = *(const uint32_t*)&g_q[qb1 + kc * 16 + 2 * t];
            qa[kc][2] = *(const uint32_t*)&g_q[qb0 + kc * 16 + 8 + 2 * t];
            qa[kc][3] = *(const uint32_t*)&g_q[qb1 + kc * 16 + 8 + 2 * t];
        }
    }

    float o[8][4];
    #pragma unroll
    for (int i = 0; i < 8; i++)
        #pragma unroll
        for (int r = 0; r < 4; r++) o[i][r] = 0.f;
    float m0 = -1e30f, m1 = -1e30f, l0 = 0.f, l1 = 0.f;

    const int ntiles = 2 * qb + 2;

    auto prefetch = [&](int tile, int s) {
        const int kt0 = tile * 64;
        #pragma unroll
        for (int i = 0; i < 2; i++) {
            int id = tid + i * 256;
            int r = id >> 3, j = id & 7;
            cp16(Ks + s * K_ST + r * TSTR + j * 16,
                 (const char*)&g_k[((size_t)(b * TT + kt0 + r)) * CC + h * HD] + j * 16);
            cp16(Vt + s * K_ST + r * TSTR + j * 16,
                 (const char*)&g_vt[((size_t)(b * HH + h) * HD + r) * TT + kt0] + j * 16);
        }
        CP_COMMIT();
    };

    prefetch(0, 0);

    for (int tile = 0; tile < ntiles; tile++) {
        const int s = tile & 1;
        const int kt0 = tile * 64;
        if (tile + 1 < ntiles) {
            prefetch(tile + 1, s ^ 1);
            asm volatile("cp.async.wait_group 1;");
        } else {
            asm volatile("cp.async.wait_group 0;");
        }
        __syncthreads();

        const char* Kc = Ks + s * K_ST;
        const char* Vc = Vt + s * K_ST;

        // S = Q K^T  (contract over d: 4 k16 groups)
        float sf[8][4];
        #pragma unroll
        for (int i = 0; i < 8; i++)
            #pragma unroll
            for (int r = 0; r < 4; r++) sf[i][r] = 0.f;
        #pragma unroll
        for (int kc = 0; kc < 4; kc++) {
            #pragma unroll
            for (int nt = 0; nt < 8; nt++) {
                uint2 bb = *(const uint2*)(Kc + (nt * 8 + g) * TSTR + kc * 32 + t * 8);
                mma_f16(sf[nt], qa[kc][0], qa[kc][1], qa[kc][2], qa[kc][3], bb.x, bb.y);
            }
        }

        // causal mask (diagonal tiles only)
        if (tile >= 2 * qb) {
            const int q0 = qt0 + wrow + g;
            const int q1 = q0 + 8;
            #pragma unroll
            for (int nt = 0; nt < 8; nt++) {
                int kcol = kt0 + nt * 8 + 2 * t;
                if (kcol     > q0) sf[nt][0] = -1e30f;
                if (kcol + 1 > q0) sf[nt][1] = -1e30f;
                if (kcol     > q1) sf[nt][2] = -1e30f;
                if (kcol + 1 > q1) sf[nt][3] = -1e30f;
            }
        }

        // online softmax (rows g and g+8)
        float mt0 = -1e30f, mt1 = -1e30f;
        #pragma unroll
        for (int nt = 0; nt < 8; nt++) {
            mt0 = fmaxf(mt0, fmaxf(sf[nt][0], sf[nt][1]));
            mt1 = fmaxf(mt1, fmaxf(sf[nt][2], sf[nt][3]));
        }
        mt0 = fmaxf(mt0, __shfl_xor_sync(0xffffffffu, mt0, 1));
        mt0 = fmaxf(mt0, __shfl_xor_sync(0xffffffffu, mt0, 2));
        mt1 = fmaxf(mt1, __shfl_xor_sync(0xffffffffu, mt1, 1));
        mt1 = fmaxf(mt1, __shfl_xor_sync(0xffffffffu, mt1, 2));

        const float mn0 = fmaxf(m0, mt0);
        const float mn1 = fmaxf(m1, mt1);
        const float c0 = __expf(m0 - mn0);
        const float c1 = __expf(m1 - mn1);
        float sum0 = 0.f, sum1 = 0.f;
        #pragma unroll
        for (int nt = 0; nt < 8; nt++) {
            sf[nt][0] = __expf(sf[nt][0] - mn0); sum0 += sf[nt][0];
            sf[nt][1] = __expf(sf[nt][1] - mn0); sum0 += sf[nt][1];
            sf[nt][2] = __expf(sf[nt][2] - mn1); sum1 += sf[nt][2];
            sf[nt][3] = __expf(sf[nt][3] - mn1); sum1 += sf[nt][3];
        }
        sum0 += __shfl_xor_sync(0xffffffffu, sum0, 1);
        sum0 += __shfl_xor_sync(0xffffffffu, sum0, 2);
        sum1 += __shfl_xor_sync(0xffffffffu, sum1, 1);
        sum1 += __shfl_xor_sync(0xffffffffu, sum1, 2);
        l0 = l0 * c0 + sum0;
        l1 = l1 * c1 + sum1;
        m0 = mn0; m1 = mn1;

        #pragma unroll
        for (int dt = 0; dt < 8; dt++) {
            o[dt][0] *= c0; o[dt][1] *= c0;
            o[dt][2] *= c1; o[dt][3] *= c1;
        }

        // store P fp16 (j pair-permuted)
        char* pr0 = Ps + (wrow + g) * TSTR;
        char* pr1 = pr0 + 8 * TSTR;
        #pragma unroll
        for (int nt = 0; nt < 8; nt++) {
            int off = (nt >> 1) * 32 + ((nt & 1) ? (2 * t + 1) : (2 * t)) * 4;
            *(__half2*)(pr0 + off) = __floats2half2_rn(sf[nt][0], sf[nt][1]);
            *(__half2*)(pr1 + off) = __floats2half2_rn(sf[nt][2], sf[nt][3]);
        }
        __syncwarp();

        // O += P V  (contract over keys: 4 k16 groups)
        #pragma unroll
        for (int kc = 0; kc < 4; kc++) {
            uint2 pa = *(const uint2*)(pr0 + kc * 32 + t * 8);   // (a0, a2)
            uint2 pb = *(const uint2*)(pr1 + kc * 32 + t * 8);   // (a1, a3)
            #pragma unroll
            for (int dt = 0; dt < 8; dt++) {
                uint2 vv = *(const uint2*)(Vc + (dt * 8 + g) * TSTR + kc * 32 + t * 8);
                mma_f16(o[dt], pa.x, pb.x, pa.y, pb.y, vv.x, vv.y);
            }
        }
        __syncthreads();
    }

    // epilogue: att fp16, d pair-permuted for the O-GEMM
    const float inv0 = 1.f / l0;
    const float inv1 = 1.f / l1;
    const size_t ob0 = ((size_t)(b * TT + qt0 + wrow + g)) * CC + h * HD;
    const size_t ob1 = ob0 + 8 * (size_t)CC;
    #pragma unroll
    for (int dt = 0; dt < 8; dt++) {
        int dl = dt * 8 + 2 * t;
        int pos = (dl & ~15) | (pslot((dl & 15) >> 1) << 1);
        *(__half2*)&g_att[ob0 + pos] = __floats2half2_rn(o[dt][0] * inv0, o[dt][1] * inv0);
        *(__half2*)&g_att[ob1 + pos] = __floats2half2_rn(o[dt][2] * inv1, o[dt][3] * inv1);
    }
}

// ---------------------------------------------------------------------------
extern "C" void kernel_launch(void* const* d_in, const int* in_sizes, int n_in,
                              void* d_out, int out_size) {
    const float* x    = (const float*)d_in[0];   // [2,2048,1024]
    const float* Wqkv = (const float*)d_in[1];   // [1024,3072]
    const float* Wo   = (const float*)d_in[2];   // [1024,1024]
    float* out = (float*)d_out;                  // [2,2048,1024]

    __half *xp, *wqt, *wot, *att;
    cudaGetSymbolAddress((void**)&xp,  g_xp);
    cudaGetSymbolAddress((void**)&wqt, g_wqt);
    cudaGetSymbolAddress((void**)&wot, g_wot);
    cudaGetSymbolAddress((void**)&att, g_att);

    static int inited = 0;
    if (!inited) {
        cudaFuncSetAttribute(tgemm_f16, cudaFuncAttributeMaxDynamicSharedMemorySize, GSMEM);
        cudaFuncSetAttribute(attn_f16,  cudaFuncAttributeMaxDynamicSharedMemorySize, ASMEM);
        inited = 1;
    }

    // 0) prep: fp16 + pair-permute
    perm_half<<<(ROWS * CC / 16 + 255) / 256, 256>>>((const float4*)x, xp, ROWS * CC / 16);
    transpose_perm_half<<<dim3(C3 / 32, CC / 32), dim3(32, 8)>>>(Wqkv, wqt, CC, C3);
    transpose_perm_half<<<dim3(CC / 32, CC / 32), dim3(32, 8)>>>(Wo, wot, CC, CC);

    // 1) qkv = x @ Wqkv  (epilogue writes g_q / g_k(scaled,permuted) / g_vt)
    tgemm_f16<<<dim3(C3 / 128, ROWS / 128), 256, GSMEM>>>(xp, wqt, nullptr, C3, 1);

    // 2) fp16 tensor-core causal flash attention -> g_att
    attn_f16<<<dim3(BB * HH, TT / 128), 256, ASMEM>>>();

    // 3) out = att @ Wo  (fp32 output)
    tgemm_f16<<<dim3(CC / 128, ROWS / 128), 256, GSMEM>>>(att, wot, out, CC, 0);
}

// round 11
// speedup vs baseline: 1.8617x; 1.0078x over previous
#include <cuda_runtime.h>
#include <cuda_fp16.h>
#include <cstdint>

// Problem constants
#define BB 2
#define TT 2048
#define CC 1024
#define HH 16
#define HD 64
#define ROWS 4096
#define C3 3072

// Scratch (allocation-free: __device__ globals)
__device__ __half g_q  [(size_t)ROWS * CC];       // Q fp16, natural layout
__device__ __half g_k  [(size_t)ROWS * CC];       // K fp16, x(1/32), d pair-permuted
__device__ __half g_vt [(size_t)BB * HH * HD * TT]; // V^T per (b,h): [bh][d][t'], token pair-permuted
__device__ __half g_att[(size_t)ROWS * CC];       // attention out fp16, d pair-permuted
__device__ __half g_xp [(size_t)ROWS * CC];       // x fp16, k pair-permuted
__device__ __half g_wqt[(size_t)C3 * CC];         // Wqkv^T fp16, k pair-permuted
__device__ __half g_wot[(size_t)CC * CC];         // Wo^T fp16, k pair-permuted

// ---------------------------------------------------------------------------
// helpers
// ---------------------------------------------------------------------------
__device__ __forceinline__ void mma_f16(float* d,
                                        uint32_t a0, uint32_t a1, uint32_t a2, uint32_t a3,
                                        uint32_t b0, uint32_t b1) {
    asm volatile(
        "mma.sync.aligned.m16n8k16.row.col.f32.f16.f16.f32 "
        "{%0,%1,%2,%3}, {%4,%5,%6,%7}, {%8,%9}, {%0,%1,%2,%3};"
        : "+f"(d[0]), "+f"(d[1]), "+f"(d[2]), "+f"(d[3])
        : "r"(a0), "r"(a1), "r"(a2), "r"(a3), "r"(b0), "r"(b1));
}

__device__ __forceinline__ void cp16(void* dst, const void* src) {
    uint32_t d = (uint32_t)__cvta_generic_to_shared(dst);
    asm volatile("cp.async.cg.shared.global [%0], [%1], 16;" :: "r"(d), "l"(src));
}
#define CP_COMMIT() asm volatile("cp.async.commit_group;")

// pair-permutation within 16-half groups: pair q -> slot [0,4,1,5,2,6,3,7]
__device__ __forceinline__ int pslot(int p) { return (p < 4) ? 2 * p : 2 * p - 7; }

// ---------------------------------------------------------------------------
// prep: fp16 + pair-permute over the contraction dim
// ---------------------------------------------------------------------------
__global__ void perm_half(const float4* __restrict__ in, __half* __restrict__ out, int n16) {
    int i = blockIdx.x * 256 + threadIdx.x;
    if (i < n16) {
        float a[16];
        #pragma unroll
        for (int j = 0; j < 4; j++) {
            float4 v = in[i * 4 + j];
            a[4 * j + 0] = v.x; a[4 * j + 1] = v.y;
            a[4 * j + 2] = v.z; a[4 * j + 3] = v.w;
        }
        uint32_t u[8];
        #pragma unroll
        for (int s = 0; s < 8; s++) {
            int q = (s & 1) ? (s + 7) >> 1 : s >> 1;   // inverse of pslot
            __half2 h = __floats2half2_rn(a[2 * q], a[2 * q + 1]);
            u[s] = *(uint32_t*)&h;
        }
        uint4* o = (uint4*)(out + (size_t)i * 16);
        o[0] = make_uint4(u[0], u[1], u[2], u[3]);
        o[1] = make_uint4(u[4], u[5], u[6], u[7]);
    }
}

// W [K][N] row-major -> T [N][K] fp16, k pair-permuted
__global__ void transpose_perm_half(const float* __restrict__ W, __half* __restrict__ T,
                                    int K, int N) {
    __shared__ float tile[32][33];
    int x = blockIdx.x * 32 + threadIdx.x;   // n
    int y0 = blockIdx.y * 32;                // k base
    #pragma unroll
    for (int j = threadIdx.y; j < 32; j += 8)
        tile[j][threadIdx.x] = W[(size_t)(y0 + j) * N + x];
    __syncthreads();
    int k = y0 + threadIdx.x;
    int kp = (k & ~15) | (pslot((k & 15) >> 1) << 1) | (k & 1);
    #pragma unroll
    for (int j = threadIdx.y; j < 32; j += 8) {
        int n = blockIdx.x * 32 + j;
        T[(size_t)n * K + kp] = __float2half_rn(tile[threadIdx.x][j]);
    }
}

// ---------------------------------------------------------------------------
// fp16 tensor-core GEMM, both operands K-major (K=1024), pair-permuted.
// C[M,N] = A[M,K] @ B[N,K]^T. Block 128x128, 4 warps (2x2), warp tile 64x64.
// K-chunk 64 halves (128B rows), smem stride 160B -> fragment LDS.64
// conflict-free. 2-stage cp.async. Per k16 step: 32 MMA / 16 LDS.64 (2:1).
// mode 0: C fp32 natural. mode 1: QKV epilogue (writes g_q/g_k/g_vt).
// ---------------------------------------------------------------------------
#define TSTR   160
#define TILE_B (128 * TSTR)          // 20480
#define STG_B  (2 * TILE_B)
#define GSMEM  (2 * STG_B)           // 81920

__device__ __forceinline__ void write_qkv(int r, int c, float v0, float v1) {
    if (c < CC) {
        *(__half2*)&g_q[(size_t)r * CC + c] = __floats2half2_rn(v0, v1);
    } else if (c < 2 * CC) {
        int ck = c - CC;
        int pos = (ck & ~15) | (pslot((ck & 15) >> 1) << 1);
        *(__half2*)&g_k[(size_t)r * CC + pos] = __floats2half2_rn(v0 * 0.03125f, v1 * 0.03125f);
    } else {
        int vd = c - 2 * CC;
        int bh = (r >> 11) * HH + (vd >> 6);
        int d0 = vd & 63;
        int tt = r & 2047;
        int ptt = (tt & ~15) | (pslot((tt & 15) >> 1) << 1) | (tt & 1);
        g_vt[((size_t)bh * HD + d0    ) * TT + ptt] = __float2half_rn(v0);
        g_vt[((size_t)bh * HD + d0 + 1) * TT + ptt] = __float2half_rn(v1);
    }
}

__global__ __launch_bounds__(128, 2) void tgemm_f16(const __half* __restrict__ A,
                                                    const __half* __restrict__ B,
                                                    float* __restrict__ C,
                                                    int N_out, int mode) {
    extern __shared__ char sm[];

    const int tid  = threadIdx.x;
    const int warp = tid >> 5;
    const int lane = tid & 31;
    const int g = lane >> 2;
    const int t = lane & 3;
    const int wm = (warp >> 1) * 64;
    const int wn = (warp & 1) * 64;
    const int row0 = blockIdx.y * 128;
    const int col0 = blockIdx.x * 128;

    float acc[4][8][4];
    #pragma unroll
    for (int i = 0; i < 4; i++)
        #pragma unroll
        for (int j = 0; j < 8; j++)
            #pragma unroll
            for (int r = 0; r < 4; r++) acc[i][j][r] = 0.f;

    const char* Ab = (const char*)A;
    const char* Bb = (const char*)B;

    auto stage = [&](int chunk, int s) {
        char* As = sm + s * STG_B;
        char* Bs = As + TILE_B;
        const size_t koff = (size_t)chunk * 128;   // 64 halves = 128 B
        #pragma unroll
        for (int i = 0; i < 8; i++) {
            int id = tid + i * 128;
            int r = id >> 3, j = id & 7;
            cp16(As + r * TSTR + j * 16, Ab + (size_t)(row0 + r) * 2048 + koff + j * 16);
        }
        #pragma unroll
        for (int i = 0; i < 8; i++) {
            int id = tid + i * 128;
            int r = id >> 3, j = id & 7;
            cp16(Bs + r * TSTR + j * 16, Bb + (size_t)(col0 + r) * 2048 + koff + j * 16);
        }
        CP_COMMIT();
    };

    stage(0, 0);

    for (int it = 0; it < 16; it++) {
        const int s = it & 1;
        if (it + 1 < 16) {
            stage(it + 1, s ^ 1);
            asm volatile("cp.async.wait_group 1;");
        } else {
            asm volatile("cp.async.wait_group 0;");
        }
        __syncthreads();

        const char* As = sm + s * STG_B;
        const char* Bs = As + TILE_B;

        #pragma unroll
        for (int kc = 0; kc < 4; kc++) {
            uint2 a0[4], a1[4], bf[8];
            #pragma unroll
            for (int mt = 0; mt < 4; mt++) {
                const char* p = As + (wm + mt * 16 + g) * TSTR + kc * 32 + t * 8;
                a0[mt] = *(const uint2*)p;                 // (a0, a2) row r
                a1[mt] = *(const uint2*)(p + 8 * TSTR);    // (a1, a3) row r+8
            }
            #pragma unroll
            for (int nt = 0; nt < 8; nt++)
                bf[nt] = *(const uint2*)(Bs + (wn + nt * 8 + g) * TSTR + kc * 32 + t * 8);
            #pragma unroll
            for (int mt = 0; mt < 4; mt++)
                #pragma unroll
                for (int nt = 0; nt < 8; nt++)
                    mma_f16(acc[mt][nt], a0[mt].x, a1[mt].x, a0[mt].y, a1[mt].y,
                            bf[nt].x, bf[nt].y);
        }
        __syncthreads();
    }

    #pragma unroll
    for (int mt = 0; mt < 4; mt++) {
        int r = row0 + wm + mt * 16 + g;
        #pragma unroll
        for (int nt = 0; nt < 8; nt++) {
            int c = col0 + wn + nt * 8 + 2 * t;
            if (mode == 0) {
                *(float2*)&C[(size_t)r * N_out + c]       = make_float2(acc[mt][nt][0], acc[mt][nt][1]);
                *(float2*)&C[(size_t)(r + 8) * N_out + c] = make_float2(acc[mt][nt][2], acc[mt][nt][3]);
            } else {
                write_qkv(r,     c, acc[mt][nt][0], acc[mt][nt][1]);
                write_qkv(r + 8, c, acc[mt][nt][2], acc[mt][nt][3]);
            }
        }
    }
}

// ---------------------------------------------------------------------------
// fp16 tensor-core causal flash attention (unchanged from R7 — proven).
// Block: 128 query rows of one (b,h); 8 warps x 16 rows; key tiles of 64.
// ---------------------------------------------------------------------------
#define K_ST   10240
#define ASMEM  (2 * K_ST + 2 * K_ST + 128 * TSTR)   // 61440

__global__ __launch_bounds__(256, 2) void attn_f16() {
    extern __shared__ char sm[];
    char* Ks = sm;                    // [2][10240]
    char* Vt = sm + 2 * K_ST;         // [2][10240]
    char* Ps = sm + 4 * K_ST;         // [128*160]

    const int b   = blockIdx.x >> 4;
    const int h   = blockIdx.x & 15;
    const int qb  = (gridDim.y - 1) - blockIdx.y;    // heavy blocks first
    const int qt0 = qb * 128;
    const int tid  = threadIdx.x;
    const int warp = tid >> 5;
    const int lane = tid & 31;
    const int g = lane >> 2;
    const int t = lane & 3;
    const int wrow = warp * 16;

    uint32_t qa[4][4];
    {
        const size_t qb0 = ((size_t)(b * TT + qt0 + wrow + g)) * CC + h * HD;
        const size_t qb1 = qb0 + 8 * (size_t)CC;
        #pragma unroll
        for (int kc = 0; kc < 4; kc++) {
            qa[kc][0] = *(const uint32_t*)&g_q[qb0 + kc * 16 + 2 * t];
            qa[kc][1] = *(const uint32_t*)&g_q[qb1 + kc * 16 + 2 * t];
            qa[kc][2] = *(const uint32_t*)&g_q[qb0 + kc * 16 + 8 + 2 * t];
            qa[kc][3] = *(const uint32_t*)&g_q[qb1 + kc * 16 + 8 + 2 * t];
        }
    }

    float o[8][4];
    #pragma unroll
    for (int i = 0; i < 8; i++)
        #pragma unroll
        for (int r = 0; r < 4; r++) o[i][r] = 0.f;
    float m0 = -1e30f, m1 = -1e30f, l0 = 0.f, l1 = 0.f;

    const int ntiles = 2 * qb + 2;

    auto prefetch = [&](int tile, int s) {
        const int kt0 = tile * 64;
        #pragma unroll
        for (int i = 0; i < 2; i++) {
            int id = tid + i * 256;
            int r = id >> 3, j = id & 7;
            cp16(Ks + s * K_ST + r * TSTR + j * 16,
                 (const char*)&g_k[((size_t)(b * TT + kt0 + r)) * CC + h * HD] + j * 16);
            cp16(Vt + s * K_ST + r * TSTR + j * 16,
                 (const char*)&g_vt[((size_t)(b * HH + h) * HD + r) * TT + kt0] + j * 16);
        }
        CP_COMMIT();
    };

    prefetch(0, 0);

    for (int tile = 0; tile < ntiles; tile++) {
        const int s = tile & 1;
        const int kt0 = tile * 64;
        if (tile + 1 < ntiles) {
            prefetch(tile + 1, s ^ 1);
            asm volatile("cp.async.wait_group 1;");
        } else {
            asm volatile("cp.async.wait_group 0;");
        }
        __syncthreads();

        const char* Kc = Ks + s * K_ST;
        const char* Vc = Vt + s * K_ST;

        float sf[8][4];
        #pragma unroll
        for (int i = 0; i < 8; i++)
            #pragma unroll
            for (int r = 0; r < 4; r++) sf[i][r] = 0.f;
        #pragma unroll
        for (int kc = 0; kc < 4; kc++) {
            #pragma unroll
            for (int nt = 0; nt < 8; nt++) {
                uint2 bb = *(const uint2*)(Kc + (nt * 8 + g) * TSTR + kc * 32 + t * 8);
                mma_f16(sf[nt], qa[kc][0], qa[kc][1], qa[kc][2], qa[kc][3], bb.x, bb.y);
            }
        }

        if (tile >= 2 * qb) {
            const int q0 = qt0 + wrow + g;
            const int q1 = q0 + 8;
            #pragma unroll
            for (int nt = 0; nt < 8; nt++) {
                int kcol = kt0 + nt * 8 + 2 * t;
                if (kcol     > q0) sf[nt][0] = -1e30f;
                if (kcol + 1 > q0) sf[nt][1] = -1e30f;
                if (kcol     > q1) sf[nt][2] = -1e30f;
                if (kcol + 1 > q1) sf[nt][3] = -1e30f;
            }
        }

        float mt0 = -1e30f, mt1 = -1e30f;
        #pragma unroll
        for (int nt = 0; nt < 8; nt++) {
            mt0 = fmaxf(mt0, fmaxf(sf[nt][0], sf[nt][1]));
            mt1 = fmaxf(mt1, fmaxf(sf[nt][2], sf[nt][3]));
        }
        mt0 = fmaxf(mt0, __shfl_xor_sync(0xffffffffu, mt0, 1));
        mt0 = fmaxf(mt0, __shfl_xor_sync(0xffffffffu, mt0, 2));
        mt1 = fmaxf(mt1, __shfl_xor_sync(0xffffffffu, mt1, 1));
        mt1 = fmaxf(mt1, __shfl_xor_sync(0xffffffffu, mt1, 2));

        const float mn0 = fmaxf(m0, mt0);
        const float mn1 = fmaxf(m1, mt1);
        const float c0 = __expf(m0 - mn0);
        const float c1 = __expf(m1 - mn1);
        float sum0 = 0.f, sum1 = 0.f;
        #pragma unroll
        for (int nt = 0; nt < 8; nt++) {
            sf[nt][0] = __expf(sf[nt][0] - mn0); sum0 += sf[nt][0];
            sf[nt][1] = __expf(sf[nt][1] - mn0); sum0 += sf[nt][1];
            sf[nt][2] = __expf(sf[nt][2] - mn1); sum1 += sf[nt][2];
            sf[nt][3] = __expf(sf[nt][3] - mn1); sum1 += sf[nt][3];
        }
        sum0 += __shfl_xor_sync(0xffffffffu, sum0, 1);
        sum0 += __shfl_xor_sync(0xffffffffu, sum0, 2);
        sum1 += __shfl_xor_sync(0xffffffffu, sum1, 1);
        sum1 += __shfl_xor_sync(0xffffffffu, sum1, 2);
        l0 = l0 * c0 + sum0;
        l1 = l1 * c1 + sum1;
        m0 = mn0; m1 = mn1;

        #pragma unroll
        for (int dt = 0; dt < 8; dt++) {
            o[dt][0] *= c0; o[dt][1] *= c0;
            o[dt][2] *= c1; o[dt][3] *= c1;
        }

        char* pr0 = Ps + (wrow + g) * TSTR;
        char* pr1 = pr0 + 8 * TSTR;
        #pragma unroll
        for (int nt = 0; nt < 8; nt++) {
            int off = (nt >> 1) * 32 + ((nt & 1) ? (2 * t + 1) : (2 * t)) * 4;
            *(__half2*)(pr0 + off) = __floats2half2_rn(sf[nt][0], sf[nt][1]);
            *(__half2*)(pr1 + off) = __floats2half2_rn(sf[nt][2], sf[nt][3]);
        }
        __syncwarp();

        #pragma unroll
        for (int kc = 0; kc < 4; kc++) {
            uint2 pa = *(const uint2*)(pr0 + kc * 32 + t * 8);
            uint2 pb = *(const uint2*)(pr1 + kc * 32 + t * 8);
            #pragma unroll
            for (int dt = 0; dt < 8; dt++) {
                uint2 vv = *(const uint2*)(Vc + (dt * 8 + g) * TSTR + kc * 32 + t * 8);
                mma_f16(o[dt], pa.x, pb.x, pa.y, pb.y, vv.x, vv.y);
            }
        }
        __syncthreads();
    }

    const float inv0 = 1.f / l0;
    const float inv1 = 1.f / l1;
    const size_t ob0 = ((size_t)(b * TT + qt0 + wrow + g)) * CC + h * HD;
    const size_t ob1 = ob0 + 8 * (size_t)CC;
    #pragma unroll
    for (int dt = 0; dt < 8; dt++) {
        int dl = dt * 8 + 2 * t;
        int pos = (dl & ~15) | (pslot((dl & 15) >> 1) << 1);
        *(__half2*)&g_att[ob0 + pos] = __floats2half2_rn(o[dt][0] * inv0, o[dt][1] * inv0);
        *(__half2*)&g_att[ob1 + pos] = __floats2half2_rn(o[dt][2] * inv1, o[dt][3] * inv1);
    }
}

// ---------------------------------------------------------------------------
extern "C" void kernel_launch(void* const* d_in, const int* in_sizes, int n_in,
                              void* d_out, int out_size) {
    const float* x    = (const float*)d_in[0];   // [2,2048,1024]
    const float* Wqkv = (const float*)d_in[1];   // [1024,3072]
    const float* Wo   = (const float*)d_in[2];   // [1024,1024]
    float* out = (float*)d_out;                  // [2,2048,1024]

    __half *xp, *wqt, *wot, *att;
    cudaGetSymbolAddress((void**)&xp,  g_xp);
    cudaGetSymbolAddress((void**)&wqt, g_wqt);
    cudaGetSymbolAddress((void**)&wot, g_wot);
    cudaGetSymbolAddress((void**)&att, g_att);

    static int inited = 0;
    if (!inited) {
        cudaFuncSetAttribute(tgemm_f16, cudaFuncAttributeMaxDynamicSharedMemorySize, GSMEM);
        cudaFuncSetAttribute(attn_f16,  cudaFuncAttributeMaxDynamicSharedMemorySize, ASMEM);
        inited = 1;
    }

    // 0) prep: fp16 + pair-permute
    perm_half<<<(ROWS * CC / 16 + 255) / 256, 256>>>((const float4*)x, xp, ROWS * CC / 16);
    transpose_perm_half<<<dim3(C3 / 32, CC / 32), dim3(32, 8)>>>(Wqkv, wqt, CC, C3);
    transpose_perm_half<<<dim3(CC / 32, CC / 32), dim3(32, 8)>>>(Wo, wot, CC, CC);

    // 1) qkv = x @ Wqkv  (epilogue writes g_q / g_k(scaled,permuted) / g_vt)
    tgemm_f16<<<dim3(C3 / 128, ROWS / 128), 128, GSMEM>>>(xp, wqt, nullptr, C3, 1);

    // 2) fp16 tensor-core causal flash attention -> g_att
    attn_f16<<<dim3(BB * HH, TT / 128), 256, ASMEM>>>();

    // 3) out = att @ Wo  (fp32 output)
    tgemm_f16<<<dim3(CC / 128, ROWS / 128), 128, GSMEM>>>(att, wot, out, CC, 0);
}